// round 12
// baseline (speedup 1.0000x reference)
#include <cuda_runtime.h>
#include <cuda_bf16.h>
#include <stdint.h>

#define N_NODES 100000
#define IN_F 256
#define OUT_F 64

// Scratch: support, CSR row pointers, pre-packed W fragments (lane-major).
__device__ float g_support[(size_t)N_NODES * OUT_F];
__device__ int   g_row_ptr[N_NODES + 1];
// [kc][ (s&3)*256 + lane*8 + j ] as uint2, stored as uint4[512] for 16B align.
__device__ uint4 g_wfrag_hi[4][512];
__device__ uint4 g_wfrag_lo[4][512];

// ===========================================================================
// Common helpers
// ===========================================================================
#define MMA_BF16(d, a, b0, b1) \
    asm volatile("mma.sync.aligned.m16n8k16.row.col.f32.bf16.bf16.f32 " \
        "{%0,%1,%2,%3}, {%4,%5,%6,%7}, {%8,%9}, {%0,%1,%2,%3};" \
        : "+f"((d)[0]), "+f"((d)[1]), "+f"((d)[2]), "+f"((d)[3]) \
        : "r"((a)[0]), "r"((a)[1]), "r"((a)[2]), "r"((a)[3]), "r"(b0), "r"(b1))

// Split pair (x,y) -> packed bf16x2 hi (truncated) + packed bf16x2 lo (rounded).
__device__ __forceinline__ uint32_t split2(float x, float y, uint32_t& lo2) {
    uint32_t bx = __float_as_uint(x), by = __float_as_uint(y), hp;
    asm("prmt.b32 %0, %1, %2, 0x7632;" : "=r"(hp) : "r"(bx), "r"(by));
    float hx = __uint_as_float(bx & 0xFFFF0000u);
    float hy = __uint_as_float(by & 0xFFFF0000u);
    float lx = x - hx, ly = y - hy;
    asm("cvt.rn.bf16x2.f32 %0, %1, %2;" : "=r"(lo2) : "f"(ly), "f"(lx));
    return hp;
}

// ===========================================================================
// One-shot W fragment packer, LANE-MAJOR layout:
//   uint2 element index = (s&3)*256 + t*8 + jg   (t = lane, jg = j 0..7)
//   b0={W[k][n],W[k+1][n]}, b1={W[k+8][n],W[k+9][n]},
//   k = kc*64 + s*16 + (t&3)*2 ; n = jg*8 + (t>>2)
// Per lane, jg 0..7 are contiguous -> GEMM reads 4 frags via 2x LDG.128.
// ===========================================================================
__global__ __launch_bounds__(256) void pack_w_kernel(const float* __restrict__ W)
{
    int idx = blockIdx.x * 256 + threadIdx.x;   // 0..4095
    int jg = idx & 7;
    int t  = (idx >> 3) & 31;
    int s  = (idx >> 8) & 3;
    int kc = idx >> 10;
    int k = kc * 64 + s * 16 + (t & 3) * 2;
    int n = jg * 8 + (t >> 2);
    float w00 = W[(size_t)k * OUT_F + n];
    float w01 = W[(size_t)(k + 1) * OUT_F + n];
    float w10 = W[(size_t)(k + 8) * OUT_F + n];
    float w11 = W[(size_t)(k + 9) * OUT_F + n];
    uint32_t l0, l1;
    uint32_t h0 = split2(w00, w01, l0);
    uint32_t h1 = split2(w10, w11, l1);
    int e = s * 256 + t * 8 + jg;               // uint2 index
    reinterpret_cast<uint2*>(g_wfrag_hi[kc])[e] = make_uint2(h0, h1);
    reinterpret_cast<uint2*>(g_wfrag_lo[kc])[e] = make_uint2(l0, l1);
}

// ===========================================================================
// GEMM + tanh, bf16 3-product split, DIRECT-GMEM register MMA:
// no smem, no barriers. A fragments loaded as sector-aligned LDG.64
// (4 lanes x 8B = full 32B sector) and split to hi/lo in registers.
// W fragments from the L2-resident lane-major table via 4x LDG.128/k-step.
// Block 128 thr (4 warps): warp w -> rows (w&1)*16, cols (w>>1)*32.
// Tile 32 rows/block, grid 3125. Per-warp independent -> max DRAM MLP.
// ===========================================================================
__global__ __launch_bounds__(128, 6) void gemm_mma_kernel(
    const float* __restrict__ A,
    const int* __restrict__ active, float* __restrict__ C, int M)
{
    const int tid = threadIdx.x;
    const int w = tid >> 5;
    const int lane = tid & 31;
    const int wm = w & 1;
    const int wn = w >> 1;
    const int row0 = blockIdx.x * 32;

    const int r0 = row0 + wm * 16 + (lane >> 2);
    const int r1 = r0 + 8;
    const bool ok0 = r0 < M, ok1 = r1 < M;
    const float* a0p = A + (size_t)(ok0 ? r0 : 0) * IN_F + (lane & 3) * 2;
    const float* a1p = A + (size_t)(ok1 ? r1 : 0) * IN_F + (lane & 3) * 2;

    float d[4][4];
    #pragma unroll
    for (int j = 0; j < 4; j++)
        #pragma unroll
        for (int e = 0; e < 4; e++) d[j][e] = 0.f;

    #pragma unroll
    for (int s = 0; s < 16; s++) {
        const int k0 = s * 16;
        float2 p00 = __ldg(reinterpret_cast<const float2*>(a0p + k0));
        float2 p10 = __ldg(reinterpret_cast<const float2*>(a1p + k0));
        float2 p01 = __ldg(reinterpret_cast<const float2*>(a0p + k0 + 8));
        float2 p11 = __ldg(reinterpret_cast<const float2*>(a1p + k0 + 8));
        if (!ok0) { p00 = make_float2(0.f, 0.f); p01 = make_float2(0.f, 0.f); }
        if (!ok1) { p10 = make_float2(0.f, 0.f); p11 = make_float2(0.f, 0.f); }

        uint32_t ah[4], al[4];
        ah[0] = split2(p00.x, p00.y, al[0]);
        ah[1] = split2(p10.x, p10.y, al[1]);
        ah[2] = split2(p01.x, p01.y, al[2]);
        ah[3] = split2(p11.x, p11.y, al[3]);

        // W fragments: 4 j-frags contiguous per lane -> 2 LDG.128 each comp.
        const int ubase = ((s & 3) * 256 + lane * 8 + wn * 4) >> 1; // uint4 idx
        const uint4* whp = &g_wfrag_hi[s >> 2][ubase];
        const uint4* wlp = &g_wfrag_lo[s >> 2][ubase];
        uint4 h01 = __ldg(whp);
        uint4 h23 = __ldg(whp + 1);
        uint4 l01 = __ldg(wlp);
        uint4 l23 = __ldg(wlp + 1);

        MMA_BF16(d[0], ah, h01.x, h01.y);
        MMA_BF16(d[0], al, h01.x, h01.y);
        MMA_BF16(d[0], ah, l01.x, l01.y);

        MMA_BF16(d[1], ah, h01.z, h01.w);
        MMA_BF16(d[1], al, h01.z, h01.w);
        MMA_BF16(d[1], ah, l01.z, l01.w);

        MMA_BF16(d[2], ah, h23.x, h23.y);
        MMA_BF16(d[2], al, h23.x, h23.y);
        MMA_BF16(d[2], ah, l23.x, l23.y);

        MMA_BF16(d[3], ah, h23.z, h23.w);
        MMA_BF16(d[3], al, h23.z, h23.w);
        MMA_BF16(d[3], ah, l23.z, l23.w);
    }

    // ---- epilogue: tanh + store ----
    const int act = *active;
    const int colb = wn * 32 + (lane & 3) * 2;
    #pragma unroll
    for (int j = 0; j < 4; j++) {
        float2 p0 = make_float2(d[j][0], d[j][1]);
        float2 p1 = make_float2(d[j][2], d[j][3]);
        if (act) {
            p0.x = tanhf(p0.x); p0.y = tanhf(p0.y);
            p1.x = tanhf(p1.x); p1.y = tanhf(p1.y);
        }
        int col = colb + j * 8;
        if (ok0)
            *reinterpret_cast<float2*>(&C[(size_t)r0 * OUT_F + col]) = p0;
        if (ok1)
            *reinterpret_cast<float2*>(&C[(size_t)r1 * OUT_F + col]) = p1;
    }
}

// ---------------------------------------------------------------------------
// Build CSR row_ptr from sorted COO rows (covers gaps + tail, deterministic).
// ---------------------------------------------------------------------------
__global__ __launch_bounds__(256) void build_rowptr_kernel(
    const int* __restrict__ rows, int nE, int nRows, int* __restrict__ rp)
{
    int e = blockIdx.x * blockDim.x + threadIdx.x;
    if (e >= nE) return;
    int r = rows[e];
    int rprev = (e == 0) ? -1 : rows[e - 1];
    for (int q = rprev + 1; q <= r; q++) rp[q] = e;
    if (e == nE - 1) {
        for (int q = r + 1; q <= nRows; q++) rp[q] = nE;
    }
}

// ---------------------------------------------------------------------------
// Row-parallel SpMM, half-warp per edge (EXACT R7 version — proven 37.6us).
// ---------------------------------------------------------------------------
__global__ __launch_bounds__(256) void spmm_row_kernel(
    const int* __restrict__ rp, const int* __restrict__ cols,
    const float* __restrict__ vals, const float* __restrict__ x,
    float* __restrict__ y, int nRows)
{
    const int row = (blockIdx.x * blockDim.x + threadIdx.x) >> 5;
    if (row >= nRows) return;
    const int lane = threadIdx.x & 31;
    const int half = lane >> 4;      // which edge of the pair
    const int fl = (lane & 15) << 2; // feature quad

    const int s = rp[row];
    const int e = rp[row + 1];

    float4 acc = make_float4(0.f, 0.f, 0.f, 0.f);
    int b = s + half;
    for (; b + 2 < e; b += 4) {
        int   c0 = __ldg(&cols[b]);
        float v0 = __ldg(&vals[b]);
        int   c1 = __ldg(&cols[b + 2]);
        float v1 = __ldg(&vals[b + 2]);
        float4 x0 = *reinterpret_cast<const float4*>(&x[(size_t)c0 * OUT_F + fl]);
        float4 x1 = *reinterpret_cast<const float4*>(&x[(size_t)c1 * OUT_F + fl]);
        acc.x = fmaf(v0, x0.x, acc.x); acc.y = fmaf(v0, x0.y, acc.y);
        acc.z = fmaf(v0, x0.z, acc.z); acc.w = fmaf(v0, x0.w, acc.w);
        acc.x = fmaf(v1, x1.x, acc.x); acc.y = fmaf(v1, x1.y, acc.y);
        acc.z = fmaf(v1, x1.z, acc.z); acc.w = fmaf(v1, x1.w, acc.w);
    }
    if (b < e) {
        int   c = __ldg(&cols[b]);
        float v = __ldg(&vals[b]);
        float4 xv = *reinterpret_cast<const float4*>(&x[(size_t)c * OUT_F + fl]);
        acc.x = fmaf(v, xv.x, acc.x); acc.y = fmaf(v, xv.y, acc.y);
        acc.z = fmaf(v, xv.z, acc.z); acc.w = fmaf(v, xv.w, acc.w);
    }

    acc.x += __shfl_xor_sync(0xffffffffu, acc.x, 16);
    acc.y += __shfl_xor_sync(0xffffffffu, acc.y, 16);
    acc.z += __shfl_xor_sync(0xffffffffu, acc.z, 16);
    acc.w += __shfl_xor_sync(0xffffffffu, acc.w, 16);

    if (half == 0)
        *reinterpret_cast<float4*>(&y[(size_t)row * OUT_F + fl]) = acc;
}

// ---------------------------------------------------------------------------
extern "C" void kernel_launch(void* const* d_in, const int* in_sizes, int n_in,
                              void* d_out, int out_size)
{
    const float* features = (const float*)d_in[0];   // [N, 256]
    const float* weight   = (const float*)d_in[1];   // [256, 64]
    const int*   adj_rows = (const int*)d_in[2];     // [E] sorted
    const int*   adj_cols = (const int*)d_in[3];     // [E]
    const float* adj_vals = (const float*)d_in[4];   // [E]
    const int*   active   = (const int*)d_in[5];     // scalar

    const int M  = in_sizes[0] / IN_F;               // 100000
    const int nE = in_sizes[2];                      // 1600000

    float* out_first  = (float*)d_out;                          // output [N,64]
    float* out_second = (float*)d_out + (size_t)M * OUT_F;      // az     [N,64]

    float* support = nullptr;
    cudaGetSymbolAddress((void**)&support, g_support);
    int* row_ptr = nullptr;
    cudaGetSymbolAddress((void**)&row_ptr, g_row_ptr);

    // 0) pre-pack W fragments + build CSR row pointers (both tiny)
    pack_w_kernel<<<16, 256>>>(weight);
    build_rowptr_kernel<<<(nE + 255) / 256, 256>>>(adj_rows, nE, M, row_ptr);

    // 1) support = tanh(features @ weight)   [direct-gmem register MMA]
    int gblocks = (M + 31) / 32;
    gemm_mma_kernel<<<gblocks, 128>>>(features, active, support, M);

    // 2) output = adj @ support
    int sblocks = (M * 32 + 255) / 256;
    spmm_row_kernel<<<sblocks, 256>>>(row_ptr, adj_cols, adj_vals, support, out_first, M);

    // 3) az = adj @ output
    spmm_row_kernel<<<sblocks, 256>>>(row_ptr, adj_cols, adj_vals, out_first, out_second, M);
}

// round 13
// speedup vs baseline: 1.3760x; 1.3760x over previous
#include <cuda_runtime.h>
#include <cuda_bf16.h>
#include <stdint.h>

#define N_NODES 100000
#define IN_F 256
#define OUT_F 64

// Scratch: support, CSR row pointers, pre-packed W fragments.
__device__ float g_support[(size_t)N_NODES * OUT_F];
__device__ int   g_row_ptr[N_NODES + 1];
__device__ uint2 g_wfrag_hi[4][1024];
__device__ uint2 g_wfrag_lo[4][1024];

// ===========================================================================
// Common helpers
// ===========================================================================
__device__ __forceinline__ uint32_t smem_u32(const void* p) {
    uint32_t a;
    asm("{ .reg .u64 t; cvta.to.shared.u64 t, %1; cvt.u32.u64 %0, t; }"
        : "=r"(a) : "l"(p));
    return a;
}

#define LDSM_X4(r, addr) \
    asm volatile("ldmatrix.sync.aligned.m8n8.x4.shared.b16 {%0,%1,%2,%3}, [%4];" \
        : "=r"((r)[0]), "=r"((r)[1]), "=r"((r)[2]), "=r"((r)[3]) : "r"(addr))

#define MMA_BF16(d, a, b0, b1) \
    asm volatile("mma.sync.aligned.m16n8k16.row.col.f32.bf16.bf16.f32 " \
        "{%0,%1,%2,%3}, {%4,%5,%6,%7}, {%8,%9}, {%0,%1,%2,%3};" \
        : "+f"((d)[0]), "+f"((d)[1]), "+f"((d)[2]), "+f"((d)[3]) \
        : "r"((a)[0]), "r"((a)[1]), "r"((a)[2]), "r"((a)[3]), "r"(b0), "r"(b1))

// Split pair (x,y) -> packed bf16x2 hi (truncated) + packed bf16x2 lo (rounded).
__device__ __forceinline__ uint32_t split2(float x, float y, uint32_t& lo2) {
    uint32_t bx = __float_as_uint(x), by = __float_as_uint(y), hp;
    asm("prmt.b32 %0, %1, %2, 0x7632;" : "=r"(hp) : "r"(bx), "r"(by));
    float hx = __uint_as_float(bx & 0xFFFF0000u);
    float hy = __uint_as_float(by & 0xFFFF0000u);
    float lx = x - hx, ly = y - hy;
    asm("cvt.rn.bf16x2.f32 %0, %1, %2;" : "=r"(lo2) : "f"(ly), "f"(lx));
    return hp;
}

// ===========================================================================
// FUSED prep: build CSR row_ptr (all threads) + pack W fragments
// (first 4096 global threads). One launch covers both independent tasks.
// W fragment id = s*256 + j*32 + t:
//   b0={W[k][n],W[k+1][n]}, b1={W[k+8][n],W[k+9][n]},
//   k = kc*64 + s*16 + (t&3)*2 ; n = j*8 + (t>>2)
// ===========================================================================
__global__ __launch_bounds__(256) void prep_kernel(
    const int* __restrict__ rows, int nE, int nRows, int* __restrict__ rp,
    const float* __restrict__ W)
{
    int gid = blockIdx.x * blockDim.x + threadIdx.x;

    if (gid < 4096) {
        int kc = gid >> 10;
        int id = gid & 1023;
        int t = id & 31;
        int j = (id >> 5) & 7;
        int s = id >> 8;
        int k = kc * 64 + s * 16 + (t & 3) * 2;
        int n = j * 8 + (t >> 2);
        float w00 = W[(size_t)k * OUT_F + n];
        float w01 = W[(size_t)(k + 1) * OUT_F + n];
        float w10 = W[(size_t)(k + 8) * OUT_F + n];
        float w11 = W[(size_t)(k + 9) * OUT_F + n];
        uint32_t l0, l1;
        uint32_t h0 = split2(w00, w01, l0);
        uint32_t h1 = split2(w10, w11, l1);
        g_wfrag_hi[kc][id] = make_uint2(h0, h1);
        g_wfrag_lo[kc][id] = make_uint2(l0, l1);
    }

    if (gid < nE) {
        int r = rows[gid];
        int rprev = (gid == 0) ? -1 : rows[gid - 1];
        for (int q = rprev + 1; q <= r; q++) rp[q] = gid;
        if (gid == nE - 1) {
            for (int q = r + 1; q <= nRows; q++) rp[q] = nE;
        }
    }
}

// ===========================================================================
// GEMM + tanh via mma.sync bf16 3-product split — R9 structure, TILE_M=64.
// smem 34KB, __launch_bounds__(256,4) -> 4 CTAs/SM, 32 warps.
// Warp wid: rows 16*(wid&3).., cols 32*(wid>>2)..  d[4][4] accumulators.
// ===========================================================================
#define TILE_M 64
#define BKC 64
#define A_ROW_BYTES 144          // 64 bf16 = 128B + 16B pad (36 words % 32 = 4)
#define A_PART (TILE_M * A_ROW_BYTES)        // 9216
#define W_PART (4 * 8 * 32 * 8)              // 8192
#define SM_AHI 0
#define SM_ALO (SM_AHI + A_PART)
#define SM_WHI (SM_ALO + A_PART)
#define SM_WLO (SM_WHI + W_PART)
#define SM_TOTAL_G (SM_WLO + W_PART)         // 34816

__global__ __launch_bounds__(256, 4) void gemm_mma_kernel(
    const float* __restrict__ A,
    const int* __restrict__ active, float* __restrict__ C, int M)
{
    extern __shared__ char sm[];
    const uint32_t sb = smem_u32(sm);
    const int tid = threadIdx.x;
    const int wid = tid >> 5;
    const int lane = tid & 31;
    const int wm = wid & 3;          // row group (16 rows)
    const int wn = wid >> 2;         // col group (32 cols)
    const int row0 = blockIdx.x * TILE_M;

    float d[4][4];
    #pragma unroll
    for (int j = 0; j < 4; j++)
        #pragma unroll
        for (int e = 0; e < 4; e++) d[j][e] = 0.f;

    const uint32_t a_lm_base =
        sb + SM_AHI + (uint32_t)(wm * 16 + (lane & 15)) * A_ROW_BYTES
        + (uint32_t)((lane >> 4) * 16);

    #pragma unroll
    for (int kc = 0; kc < 4; kc++) {
        const int kbase = kc * BKC;

        // ---- A chunk: 64 rows x 64 k (fp32 -> hi/lo bf16, PRMT split) ----
        #pragma unroll
        for (int i = 0; i < 4; i++) {
            int idx = tid + i * 256;          // 0..1023 float4s
            int r = idx >> 4;                 // 0..63
            int q = idx & 15;                 // float4 within 64-col row
            int gr = row0 + r;
            float4 v = make_float4(0.f, 0.f, 0.f, 0.f);
            if (gr < M)
                v = *reinterpret_cast<const float4*>(
                    &A[(size_t)gr * IN_F + kbase + (q << 2)]);
            uint32_t l0, l1;
            uint32_t h0 = split2(v.x, v.y, l0);
            uint32_t h1 = split2(v.z, v.w, l1);
            int off = r * A_ROW_BYTES + q * 8;
            *reinterpret_cast<uint2*>(sm + SM_AHI + off) = make_uint2(h0, h1);
            *reinterpret_cast<uint2*>(sm + SM_ALO + off) = make_uint2(l0, l1);
        }

        // ---- W chunk: linear copy of pre-packed fragments ----
        {
            const uint2* wh = g_wfrag_hi[kc];
            const uint2* wl = g_wfrag_lo[kc];
            uint2* dh = reinterpret_cast<uint2*>(sm + SM_WHI);
            uint2* dl = reinterpret_cast<uint2*>(sm + SM_WLO);
            #pragma unroll
            for (int i = 0; i < 4; i++) {
                int idx = tid + i * 256;
                dh[idx] = wh[idx];
                dl[idx] = wl[idx];
            }
        }
        __syncthreads();

        // ---- MMA: 4 k16-steps x (hi*hi + lo*hi + hi*lo), 4 j per warp ----
        #pragma unroll
        for (int s = 0; s < 4; s++) {
            uint32_t ah[4], al[4];
            LDSM_X4(ah, a_lm_base + s * 32);
            LDSM_X4(al, a_lm_base + s * 32 + (SM_ALO - SM_AHI));
            const char* whb = sm + SM_WHI + (s * 8 * 32 + wn * 4 * 32 + lane) * 8;
            const char* wlb = sm + SM_WLO + (s * 8 * 32 + wn * 4 * 32 + lane) * 8;
            #pragma unroll
            for (int j = 0; j < 4; j++) {
                uint2 bh = *reinterpret_cast<const uint2*>(whb + j * 256);
                uint2 bl = *reinterpret_cast<const uint2*>(wlb + j * 256);
                MMA_BF16(d[j], ah, bh.x, bh.y);
                MMA_BF16(d[j], al, bh.x, bh.y);
                MMA_BF16(d[j], ah, bl.x, bl.y);
            }
        }
        __syncthreads();
    }

    // ---- epilogue: tanh + store ----
    const int act = *active;
    int rlo = row0 + wm * 16 + (lane >> 2);
    int colb = wn * 32 + (lane & 3) * 2;
    #pragma unroll
    for (int j = 0; j < 4; j++) {
        float2 p0 = make_float2(d[j][0], d[j][1]);
        float2 p1 = make_float2(d[j][2], d[j][3]);
        if (act) {
            p0.x = tanhf(p0.x); p0.y = tanhf(p0.y);
            p1.x = tanhf(p1.x); p1.y = tanhf(p1.y);
        }
        int col = colb + j * 8;
        if (rlo < M)
            *reinterpret_cast<float2*>(&C[(size_t)rlo * OUT_F + col]) = p0;
        if (rlo + 8 < M)
            *reinterpret_cast<float2*>(&C[(size_t)(rlo + 8) * OUT_F + col]) = p1;
    }
}

// ---------------------------------------------------------------------------
// Row-parallel SpMM, half-warp per edge (EXACT R7 version — proven 37.6us).
// ---------------------------------------------------------------------------
__global__ __launch_bounds__(256) void spmm_row_kernel(
    const int* __restrict__ rp, const int* __restrict__ cols,
    const float* __restrict__ vals, const float* __restrict__ x,
    float* __restrict__ y, int nRows)
{
    const int row = (blockIdx.x * blockDim.x + threadIdx.x) >> 5;
    if (row >= nRows) return;
    const int lane = threadIdx.x & 31;
    const int half = lane >> 4;      // which edge of the pair
    const int fl = (lane & 15) << 2; // feature quad

    const int s = rp[row];
    const int e = rp[row + 1];

    float4 acc = make_float4(0.f, 0.f, 0.f, 0.f);
    int b = s + half;
    for (; b + 2 < e; b += 4) {
        int   c0 = __ldg(&cols[b]);
        float v0 = __ldg(&vals[b]);
        int   c1 = __ldg(&cols[b + 2]);
        float v1 = __ldg(&vals[b + 2]);
        float4 x0 = *reinterpret_cast<const float4*>(&x[(size_t)c0 * OUT_F + fl]);
        float4 x1 = *reinterpret_cast<const float4*>(&x[(size_t)c1 * OUT_F + fl]);
        acc.x = fmaf(v0, x0.x, acc.x); acc.y = fmaf(v0, x0.y, acc.y);
        acc.z = fmaf(v0, x0.z, acc.z); acc.w = fmaf(v0, x0.w, acc.w);
        acc.x = fmaf(v1, x1.x, acc.x); acc.y = fmaf(v1, x1.y, acc.y);
        acc.z = fmaf(v1, x1.z, acc.z); acc.w = fmaf(v1, x1.w, acc.w);
    }
    if (b < e) {
        int   c = __ldg(&cols[b]);
        float v = __ldg(&vals[b]);
        float4 xv = *reinterpret_cast<const float4*>(&x[(size_t)c * OUT_F + fl]);
        acc.x = fmaf(v, xv.x, acc.x); acc.y = fmaf(v, xv.y, acc.y);
        acc.z = fmaf(v, xv.z, acc.z); acc.w = fmaf(v, xv.w, acc.w);
    }

    acc.x += __shfl_xor_sync(0xffffffffu, acc.x, 16);
    acc.y += __shfl_xor_sync(0xffffffffu, acc.y, 16);
    acc.z += __shfl_xor_sync(0xffffffffu, acc.z, 16);
    acc.w += __shfl_xor_sync(0xffffffffu, acc.w, 16);

    if (half == 0)
        *reinterpret_cast<float4*>(&y[(size_t)row * OUT_F + fl]) = acc;
}

// ---------------------------------------------------------------------------
extern "C" void kernel_launch(void* const* d_in, const int* in_sizes, int n_in,
                              void* d_out, int out_size)
{
    const float* features = (const float*)d_in[0];   // [N, 256]
    const float* weight   = (const float*)d_in[1];   // [256, 64]
    const int*   adj_rows = (const int*)d_in[2];     // [E] sorted
    const int*   adj_cols = (const int*)d_in[3];     // [E]
    const float* adj_vals = (const float*)d_in[4];   // [E]
    const int*   active   = (const int*)d_in[5];     // scalar

    const int M  = in_sizes[0] / IN_F;               // 100000
    const int nE = in_sizes[2];                      // 1600000

    float* out_first  = (float*)d_out;                          // output [N,64]
    float* out_second = (float*)d_out + (size_t)M * OUT_F;      // az     [N,64]

    float* support = nullptr;
    cudaGetSymbolAddress((void**)&support, g_support);
    int* row_ptr = nullptr;
    cudaGetSymbolAddress((void**)&row_ptr, g_row_ptr);

    cudaFuncSetAttribute(gemm_mma_kernel,
                         cudaFuncAttributeMaxDynamicSharedMemorySize, SM_TOTAL_G);

    // 0) fused prep: CSR row pointers + W fragment packing (one launch)
    prep_kernel<<<(nE + 255) / 256, 256>>>(adj_rows, nE, M, row_ptr, weight);

    // 1) support = tanh(features @ weight)
    int gblocks = (M + TILE_M - 1) / TILE_M;
    gemm_mma_kernel<<<gblocks, 256, SM_TOTAL_G>>>(features, active, support, M);

    // 2) output = adj @ support
    int sblocks = (M * 32 + 255) / 256;
    spmm_row_kernel<<<sblocks, 256>>>(row_ptr, adj_cols, adj_vals, support, out_first, M);

    // 3) az = adj @ output
    spmm_row_kernel<<<sblocks, 256>>>(row_ptr, adj_cols, adj_vals, out_first, out_second, M);
}